// round 1
// baseline (speedup 1.0000x reference)
#include <cuda_runtime.h>

#define NNODES 50000
#define NEDGES 800000
#define H 128
#define FE 16
#define MF 273          // 2*H + 1 + FE
#define FPAD 276        // pad rows to multiple of 4 floats (16B) for float4 LDS
#define TILE_E 16
#define TILE_N 8

// Scratch accumulators (allocation-free: device globals)
__device__ float g_hagg[NNODES * H];   // 25.6 MB
__device__ float g_xagg[NNODES * 3];

__device__ __forceinline__ float siluf(float x) {
    return x / (1.0f + __expf(-x));
}

__global__ void zero_kernel() {
    const int stride = gridDim.x * blockDim.x;
    int idx = blockIdx.x * blockDim.x + threadIdx.x;
    for (int i = idx; i < NNODES * H; i += stride) g_hagg[i] = 0.0f;
    for (int i = idx; i < NNODES * 3; i += stride) g_xagg[i] = 0.0f;
}

__global__ __launch_bounds__(128)
void edge_kernel(const float* __restrict__ h, const float* __restrict__ coords,
                 const float* __restrict__ a, const int* __restrict__ src,
                 const int* __restrict__ dst,
                 const float* __restrict__ wc1, const float* __restrict__ bc1,
                 const float* __restrict__ wc2, const float* __restrict__ bc2,
                 const float* __restrict__ wc3,
                 const float* __restrict__ we1, const float* __restrict__ be1,
                 const float* __restrict__ we2, const float* __restrict__ be2,
                 const float* __restrict__ wa,  const float* __restrict__ ba)
{
    __shared__ __align__(16) float f_s[TILE_E][FPAD];   // [hs | hd | radial | a]
    __shared__ __align__(16) float c1_s[TILE_E][H];
    __shared__ __align__(16) float m1_s[TILE_E][H];
    __shared__ float diffs_s[TILE_E][3];
    __shared__ float rad_s[TILE_E];
    __shared__ float scale_s[TILE_E];
    __shared__ float att_s[TILE_E];
    __shared__ int   src_s[TILE_E], dst_s[TILE_E];

    const int tid  = threadIdx.x;
    const int warp = tid >> 5;
    const int lane = tid & 31;
    const int e0   = blockIdx.x * TILE_E;

    if (tid < TILE_E) {
        src_s[tid]   = src[e0 + tid];
        dst_s[tid]   = dst[e0 + tid];
        scale_s[tid] = 0.0f;
        att_s[tid]   = ba[0];
    }
    __syncthreads();

    // ---- gather phase: build f = [h[src], h[dst], radial, a] in smem ----
    for (int e = warp; e < TILE_E; e += 4) {
        const int s = src_s[e], d = dst_s[e];
        const float* hs = h + (long)s * H;
        const float* hd = h + (long)d * H;
        #pragma unroll
        for (int k = lane; k < H; k += 32) {
            f_s[e][k]     = hs[k];
            f_s[e][H + k] = hd[k];
        }
        if (lane < FE)
            f_s[e][2 * H + 1 + lane] = a[(long)(e0 + e) * FE + lane];
        if (lane < 3)
            diffs_s[e][lane] = coords[(long)s * 3 + lane] - coords[(long)d * 3 + lane];
        __syncwarp();
        if (lane == 0) {
            float dx = diffs_s[e][0], dy = diffs_s[e][1], dz = diffs_s[e][2];
            float r  = dx * dx + dy * dy + dz * dz;
            rad_s[e]    = r;
            f_s[e][2*H] = r;
        }
    }
    __syncthreads();

    const int j = tid;             // output column (0..127)
    float accC[TILE_E], accE[TILE_E];

    // ---- layer 1 (273 -> 128) for both coord-MLP and edge-MLP ----
    {
        const float bc = bc1[j], be = be1[j];
        #pragma unroll
        for (int e = 0; e < TILE_E; e++) { accC[e] = bc; accE[e] = be; }
        for (int k = 0; k < 272; k += 4) {
            const float wc0 = wc1[(k+0)*H + j], wc1v = wc1[(k+1)*H + j];
            const float wc2v = wc1[(k+2)*H + j], wc3v = wc1[(k+3)*H + j];
            const float we0 = we1[(k+0)*H + j], we1v = we1[(k+1)*H + j];
            const float we2v = we1[(k+2)*H + j], we3v = we1[(k+3)*H + j];
            #pragma unroll
            for (int e = 0; e < TILE_E; e++) {
                const float4 fv = *reinterpret_cast<const float4*>(&f_s[e][k]);
                float c = accC[e], m = accE[e];
                c = fmaf(fv.x, wc0,  c); m = fmaf(fv.x, we0,  m);
                c = fmaf(fv.y, wc1v, c); m = fmaf(fv.y, we1v, m);
                c = fmaf(fv.z, wc2v, c); m = fmaf(fv.z, we2v, m);
                c = fmaf(fv.w, wc3v, c); m = fmaf(fv.w, we3v, m);
                accC[e] = c; accE[e] = m;
            }
        }
        {   // tail k = 272
            const float wc = wc1[272*H + j], we = we1[272*H + j];
            #pragma unroll
            for (int e = 0; e < TILE_E; e++) {
                const float fv = f_s[e][272];
                accC[e] = fmaf(fv, wc, accC[e]);
                accE[e] = fmaf(fv, we, accE[e]);
            }
        }
        #pragma unroll
        for (int e = 0; e < TILE_E; e++) {
            c1_s[e][j] = siluf(accC[e]);
            m1_s[e][j] = siluf(accE[e]);
        }
    }
    __syncthreads();

    // ---- layer 2 (128 -> 128) for both MLPs; results stay in registers ----
    {
        const float bc = bc2[j], be = be2[j];
        #pragma unroll
        for (int e = 0; e < TILE_E; e++) { accC[e] = bc; accE[e] = be; }
        for (int k = 0; k < H; k += 4) {
            const float wc0 = wc2[(k+0)*H + j], wc1v = wc2[(k+1)*H + j];
            const float wc2v = wc2[(k+2)*H + j], wc3v = wc2[(k+3)*H + j];
            const float we0 = we2[(k+0)*H + j], we1v = we2[(k+1)*H + j];
            const float we2v = we2[(k+2)*H + j], we3v = we2[(k+3)*H + j];
            #pragma unroll
            for (int e = 0; e < TILE_E; e++) {
                const float4 cv = *reinterpret_cast<const float4*>(&c1_s[e][k]);
                const float4 mv = *reinterpret_cast<const float4*>(&m1_s[e][k]);
                float c = accC[e], m = accE[e];
                c = fmaf(cv.x, wc0,  c); m = fmaf(mv.x, we0,  m);
                c = fmaf(cv.y, wc1v, c); m = fmaf(mv.y, we1v, m);
                c = fmaf(cv.z, wc2v, c); m = fmaf(mv.z, we2v, m);
                c = fmaf(cv.w, wc3v, c); m = fmaf(mv.w, we3v, m);
                accC[e] = c; accE[e] = m;
            }
        }
        #pragma unroll
        for (int e = 0; e < TILE_E; e++) {
            accC[e] = siluf(accC[e]);   // c2
            accE[e] = siluf(accE[e]);   // m2
        }
    }

    // ---- heads: scale = c2 @ wc3 ; att_pre = m2 @ wa  (block reduction) ----
    {
        const float wc3j = wc3[j];
        const float waj  = wa[j];
        #pragma unroll
        for (int e = 0; e < TILE_E; e++) {
            float vs = accC[e] * wc3j;
            float va = accE[e] * waj;
            #pragma unroll
            for (int off = 16; off > 0; off >>= 1) {
                vs += __shfl_down_sync(0xffffffffu, vs, off);
                va += __shfl_down_sync(0xffffffffu, va, off);
            }
            if (lane == 0) {
                atomicAdd(&scale_s[e], vs);
                atomicAdd(&att_s[e],  va);
            }
        }
    }
    __syncthreads();

    // ---- scatter: msg_h -> g_hagg (coalesced), msg_x -> g_xagg ----
    #pragma unroll
    for (int e = 0; e < TILE_E; e++) {
        const float att = 1.0f / (1.0f + __expf(-att_s[e]));
        atomicAdd(&g_hagg[(long)dst_s[e] * H + j], att * accE[e]);
    }
    if (tid < TILE_E * 3) {
        const int e = tid / 3, c = tid % 3;
        const float v = scale_s[e] * diffs_s[e][c] / (rad_s[e] + 1.0f);
        atomicAdd(&g_xagg[(long)dst_s[e] * 3 + c], v);
    }
}

__global__ __launch_bounds__(128)
void node_kernel(const float* __restrict__ h, const float* __restrict__ coords,
                 const float* __restrict__ wn1, const float* __restrict__ bn1,
                 const float* __restrict__ wn2, const float* __restrict__ bn2,
                 float* __restrict__ out_h, float* __restrict__ out_x)
{
    __shared__ __align__(16) float hh_s[TILE_N][H];
    __shared__ __align__(16) float ha_s[TILE_N][H];
    __shared__ __align__(16) float n_s[TILE_N][H];

    const int tid  = threadIdx.x;
    const int warp = tid >> 5;
    const int lane = tid & 31;
    const int n0   = blockIdx.x * TILE_N;

    for (int e = warp; e < TILE_N; e += 4) {
        const int node = n0 + e;
        #pragma unroll
        for (int k = lane; k < H; k += 32) {
            hh_s[e][k] = h[(long)node * H + k];
            ha_s[e][k] = g_hagg[(long)node * H + k];
        }
    }
    __syncthreads();

    const int j = tid;
    float acc[TILE_N];
    {
        const float b1 = bn1[j];
        #pragma unroll
        for (int e = 0; e < TILE_N; e++) acc[e] = b1;
        for (int k = 0; k < H; k += 4) {
            const float wA0 = wn1[(k+0)*H + j], wA1 = wn1[(k+1)*H + j];
            const float wA2 = wn1[(k+2)*H + j], wA3 = wn1[(k+3)*H + j];
            const float wB0 = wn1[(H+k+0)*H + j], wB1 = wn1[(H+k+1)*H + j];
            const float wB2 = wn1[(H+k+2)*H + j], wB3 = wn1[(H+k+3)*H + j];
            #pragma unroll
            for (int e = 0; e < TILE_N; e++) {
                const float4 hv = *reinterpret_cast<const float4*>(&hh_s[e][k]);
                const float4 av = *reinterpret_cast<const float4*>(&ha_s[e][k]);
                float s = acc[e];
                s = fmaf(hv.x, wA0, s); s = fmaf(hv.y, wA1, s);
                s = fmaf(hv.z, wA2, s); s = fmaf(hv.w, wA3, s);
                s = fmaf(av.x, wB0, s); s = fmaf(av.y, wB1, s);
                s = fmaf(av.z, wB2, s); s = fmaf(av.w, wB3, s);
                acc[e] = s;
            }
        }
        #pragma unroll
        for (int e = 0; e < TILE_N; e++) n_s[e][j] = siluf(acc[e]);
    }
    __syncthreads();

    {
        const float b2 = bn2[j];
        #pragma unroll
        for (int e = 0; e < TILE_N; e++) acc[e] = b2;
        for (int k = 0; k < H; k += 4) {
            const float w0 = wn2[(k+0)*H + j], w1 = wn2[(k+1)*H + j];
            const float w2 = wn2[(k+2)*H + j], w3 = wn2[(k+3)*H + j];
            #pragma unroll
            for (int e = 0; e < TILE_N; e++) {
                const float4 nv = *reinterpret_cast<const float4*>(&n_s[e][k]);
                float s = acc[e];
                s = fmaf(nv.x, w0, s); s = fmaf(nv.y, w1, s);
                s = fmaf(nv.z, w2, s); s = fmaf(nv.w, w3, s);
                acc[e] = s;
            }
        }
        #pragma unroll
        for (int e = 0; e < TILE_N; e++)
            out_h[(long)(n0 + e) * H + j] = h[(long)(n0 + e) * H + j] + acc[e];
    }

    if (tid < TILE_N * 3) {
        const int e = tid / 3, c = tid % 3;
        const int node = n0 + e;
        out_x[(long)node * 3 + c] = coords[(long)node * 3 + c] + g_xagg[(long)node * 3 + c];
    }
}

extern "C" void kernel_launch(void* const* d_in, const int* in_sizes, int n_in,
                              void* d_out, int out_size) {
    const float* h      = (const float*)d_in[0];
    const float* coords = (const float*)d_in[1];
    const float* a      = (const float*)d_in[2];
    const int*   src    = (const int*)  d_in[3];
    const int*   dst    = (const int*)  d_in[4];
    const float* wc1 = (const float*)d_in[5];
    const float* bc1 = (const float*)d_in[6];
    const float* wc2 = (const float*)d_in[7];
    const float* bc2 = (const float*)d_in[8];
    const float* wc3 = (const float*)d_in[9];
    const float* we1 = (const float*)d_in[10];
    const float* be1 = (const float*)d_in[11];
    const float* we2 = (const float*)d_in[12];
    const float* be2 = (const float*)d_in[13];
    const float* wa  = (const float*)d_in[14];
    const float* ba  = (const float*)d_in[15];
    const float* wn1 = (const float*)d_in[16];
    const float* bn1 = (const float*)d_in[17];
    const float* wn2 = (const float*)d_in[18];
    const float* bn2 = (const float*)d_in[19];

    float* out_h = (float*)d_out;                 // [N, H]
    float* out_x = out_h + (long)NNODES * H;      // [N, 3]

    zero_kernel<<<1024, 256>>>();
    edge_kernel<<<NEDGES / TILE_E, 128>>>(h, coords, a, src, dst,
                                          wc1, bc1, wc2, bc2, wc3,
                                          we1, be1, we2, be2, wa, ba);
    node_kernel<<<NNODES / TILE_N, 128>>>(h, coords, wn1, bn1, wn2, bn2,
                                          out_h, out_x);
}

// round 2
// speedup vs baseline: 2.2057x; 2.2057x over previous
#include <cuda_runtime.h>
#include <cstdint>

#define NNODES 50000
#define NEDGES 800000
#define H 128
#define FE 16
#define TILE_M 128          // edges per CTA
#define THREADS 512
#define FSTRIDE 292         // f tile row stride (floats), 292 % 32 == 4 -> conflict-free frags
#define MIDSTRIDE 132       // layer-1 activation stride, 132 % 32 == 4
#define WSTRIDE 136         // weight chunk stride, 136 % 32 == 8
#define WCHUNK 32
#define TILE_N 8            // node kernel tile

// dynamic smem: f tile + weight staging
#define DYN_SMEM ((TILE_M * FSTRIDE + 2 * WCHUNK * WSTRIDE) * 4)

__device__ float g_hagg[NNODES * H];
__device__ float g_xagg[NNODES * 3];

__device__ __forceinline__ float siluf(float x) { return x / (1.0f + __expf(-x)); }
__device__ __forceinline__ float sigf(float x)  { return 1.0f / (1.0f + __expf(-x)); }

__device__ __forceinline__ uint32_t cvt_tf32(float x) {
    uint32_t r;
    asm("cvt.rna.tf32.f32 %0, %1;" : "=r"(r) : "f"(x));
    return r;
}

__device__ __forceinline__ void mma_tf32(float d[4], const uint32_t a[4], const uint32_t b[2]) {
    asm volatile(
        "mma.sync.aligned.m16n8k8.row.col.f32.tf32.tf32.f32 "
        "{%0,%1,%2,%3},{%4,%5,%6,%7},{%8,%9},{%0,%1,%2,%3};"
        : "+f"(d[0]), "+f"(d[1]), "+f"(d[2]), "+f"(d[3])
        : "r"(a[0]), "r"(a[1]), "r"(a[2]), "r"(a[3]), "r"(b[0]), "r"(b[1]));
}

__global__ void zero_kernel() {
    const int stride = gridDim.x * blockDim.x;
    int idx = blockIdx.x * blockDim.x + threadIdx.x;
    for (int i = idx; i < NNODES * H; i += stride) g_hagg[i] = 0.0f;
    for (int i = idx; i < NNODES * 3; i += stride) g_xagg[i] = 0.0f;
}

// Stage a 32-row x 128-col chunk of both weight matrices into smem (tf32-rounded).
__device__ __forceinline__ void stage_w(const float* __restrict__ W0,
                                        const float* __restrict__ W1,
                                        int kb, int Ktot, float* w_s, int tid) {
    #pragma unroll
    for (int it = 0; it < 4; it++) {
        int i  = tid + it * THREADS;       // 0..2047 float4 slots
        int sd = i >> 10;                  // side
        int kk = (i >> 5) & 31;            // row in chunk
        int j4 = (i & 31) << 2;            // col base
        int k  = kb + kk;
        float4 v = make_float4(0.f, 0.f, 0.f, 0.f);
        if (k < Ktot) v = *reinterpret_cast<const float4*>((sd ? W1 : W0) + k * H + j4);
        uint4 u;
        u.x = cvt_tf32(v.x); u.y = cvt_tf32(v.y); u.z = cvt_tf32(v.z); u.w = cvt_tf32(v.w);
        *reinterpret_cast<uint4*>(w_s + sd * WCHUNK * WSTRIDE + kk * WSTRIDE + j4) = u;
    }
}

__global__ __launch_bounds__(THREADS, 1)
void edge_kernel(const float* __restrict__ h, const float* __restrict__ coords,
                 const float* __restrict__ a, const int* __restrict__ src,
                 const int* __restrict__ dst,
                 const float* __restrict__ wc1, const float* __restrict__ bc1,
                 const float* __restrict__ wc2, const float* __restrict__ bc2,
                 const float* __restrict__ wc3,
                 const float* __restrict__ we1, const float* __restrict__ be1,
                 const float* __restrict__ we2, const float* __restrict__ be2,
                 const float* __restrict__ wa,  const float* __restrict__ ba)
{
    extern __shared__ float smem[];
    float* f_s = smem;                              // [128][FSTRIDE]
    float* w_s = smem + TILE_M * FSTRIDE;           // [2][32][WSTRIDE]
    // layer-1 activations alias the f tile (f dead after layer-1 mainloop)
    float* mid_base = smem;                         // [2][128][MIDSTRIDE]

    __shared__ float diffs_s[TILE_M][3];
    __shared__ float rad_s[TILE_M];
    __shared__ float scale_s[TILE_M];
    __shared__ float att_s[TILE_M];
    __shared__ int   src_s[TILE_M], dst_s[TILE_M];

    const int tid   = threadIdx.x;
    const int wid   = tid >> 5;
    const int lane  = tid & 31;
    const int g     = lane >> 2;          // groupID
    const int tig   = lane & 3;           // threadID in group
    const int side  = wid >> 3;           // 0=coord MLP, 1=edge MLP
    const int wloc  = wid & 7;
    const int mBase = (wloc >> 1) * 32;   // 0,32,64,96
    const int nBase = (wloc & 1) * 64;    // 0,64
    const int e0    = blockIdx.x * TILE_M;

    // ---- per-warp prologue: indices + small-array init ----
    {
        const int eb = wid * 8;
        if (lane < 8)        src_s[eb + lane]        = src[e0 + eb + lane];
        else if (lane < 16)  dst_s[eb + lane - 8]    = dst[e0 + eb + lane - 8];
        else if (lane < 24)  scale_s[eb + lane - 16] = 0.0f;
        else                 att_s[eb + lane - 24]   = ba[0];
        __syncwarp();
        // gather 8 edges per warp
        for (int e = eb; e < eb + 8; e++) {
            const int s = src_s[e], d = dst_s[e];
            float4 hv = reinterpret_cast<const float4*>(h + (long)s * H)[lane];
            float4 dv = reinterpret_cast<const float4*>(h + (long)d * H)[lane];
            uint4 u;
            u.x = cvt_tf32(hv.x); u.y = cvt_tf32(hv.y); u.z = cvt_tf32(hv.z); u.w = cvt_tf32(hv.w);
            *reinterpret_cast<uint4*>(f_s + e * FSTRIDE + lane * 4) = u;
            u.x = cvt_tf32(dv.x); u.y = cvt_tf32(dv.y); u.z = cvt_tf32(dv.z); u.w = cvt_tf32(dv.w);
            *reinterpret_cast<uint4*>(f_s + e * FSTRIDE + H + lane * 4) = u;
            if (lane < 16)
                f_s[e * FSTRIDE + 257 + lane] =
                    __uint_as_float(cvt_tf32(a[(long)(e0 + e) * FE + lane]));
            else if (lane >= 17)
                f_s[e * FSTRIDE + 273 + (lane - 17)] = 0.0f;   // zero-pad to 288
            if (lane < 3)
                diffs_s[e][lane] = coords[(long)s * 3 + lane] - coords[(long)d * 3 + lane];
            __syncwarp();
            if (lane == 0) {
                float dx = diffs_s[e][0], dy = diffs_s[e][1], dz = diffs_s[e][2];
                float r = dx * dx + dy * dy + dz * dz;
                rad_s[e] = r;
                f_s[e * FSTRIDE + 256] = __uint_as_float(cvt_tf32(r));
            }
        }
    }

    float acc[2][8][4];
    #pragma unroll
    for (int mf = 0; mf < 2; mf++)
        #pragma unroll
        for (int nf = 0; nf < 8; nf++)
            #pragma unroll
            for (int q = 0; q < 4; q++) acc[mf][nf][q] = 0.0f;

    const float* w_side = w_s + side * WCHUNK * WSTRIDE;

    // ================= layer 1: [128 x 288] @ [288 x 128] =================
    for (int chunk = 0; chunk < 9; chunk++) {
        const int kb = chunk * WCHUNK;
        __syncthreads();
        stage_w(wc1, we1, kb, 273, w_s, tid);
        __syncthreads();
        #pragma unroll
        for (int ks = 0; ks < 4; ks++) {
            const int k0 = kb + ks * 8;
            uint32_t A[2][4];
            #pragma unroll
            for (int mf = 0; mf < 2; mf++) {
                const float* fr  = f_s + (mBase + mf * 16 + g) * FSTRIDE;
                const float* fr8 = fr + 8 * FSTRIDE;
                A[mf][0] = __float_as_uint(fr [k0 + tig]);
                A[mf][1] = __float_as_uint(fr8[k0 + tig]);
                A[mf][2] = __float_as_uint(fr [k0 + tig + 4]);
                A[mf][3] = __float_as_uint(fr8[k0 + tig + 4]);
            }
            const float* wb  = w_side + (ks * 8 + tig) * WSTRIDE;
            const float* wb4 = wb + 4 * WSTRIDE;
            uint32_t B[8][2];
            #pragma unroll
            for (int nf = 0; nf < 8; nf++) {
                const int n = nBase + nf * 8 + g;
                B[nf][0] = __float_as_uint(wb [n]);
                B[nf][1] = __float_as_uint(wb4[n]);
            }
            #pragma unroll
            for (int mf = 0; mf < 2; mf++)
                #pragma unroll
                for (int nf = 0; nf < 8; nf++)
                    mma_tf32(acc[mf][nf], A[mf], B[nf]);
        }
    }

    // ---- layer-1 epilogue: bias + silu -> mid (aliases f tile) ----
    __syncthreads();
    float* mid = mid_base + side * TILE_M * MIDSTRIDE;
    {
        const float* b1 = side ? be1 : bc1;
        #pragma unroll
        for (int mf = 0; mf < 2; mf++) {
            float* r0 = mid + (mBase + mf * 16 + g) * MIDSTRIDE;
            float* r1 = r0 + 8 * MIDSTRIDE;
            #pragma unroll
            for (int nf = 0; nf < 8; nf++) {
                const int c0 = nBase + nf * 8 + 2 * tig;
                const float bv0 = b1[c0], bv1 = b1[c0 + 1];
                r0[c0]     = __uint_as_float(cvt_tf32(siluf(acc[mf][nf][0] + bv0)));
                r0[c0 + 1] = __uint_as_float(cvt_tf32(siluf(acc[mf][nf][1] + bv1)));
                r1[c0]     = __uint_as_float(cvt_tf32(siluf(acc[mf][nf][2] + bv0)));
                r1[c0 + 1] = __uint_as_float(cvt_tf32(siluf(acc[mf][nf][3] + bv1)));
                #pragma unroll
                for (int q = 0; q < 4; q++) acc[mf][nf][q] = 0.0f;
            }
        }
    }

    // ================= layer 2: [128 x 128] @ [128 x 128] =================
    for (int chunk = 0; chunk < 4; chunk++) {
        const int kb = chunk * WCHUNK;
        __syncthreads();
        stage_w(wc2, we2, kb, 128, w_s, tid);
        __syncthreads();
        #pragma unroll
        for (int ks = 0; ks < 4; ks++) {
            const int k0 = kb + ks * 8;
            uint32_t A[2][4];
            #pragma unroll
            for (int mf = 0; mf < 2; mf++) {
                const float* fr  = mid + (mBase + mf * 16 + g) * MIDSTRIDE;
                const float* fr8 = fr + 8 * MIDSTRIDE;
                A[mf][0] = __float_as_uint(fr [k0 + tig]);
                A[mf][1] = __float_as_uint(fr8[k0 + tig]);
                A[mf][2] = __float_as_uint(fr [k0 + tig + 4]);
                A[mf][3] = __float_as_uint(fr8[k0 + tig + 4]);
            }
            const float* wb  = w_side + (ks * 8 + tig) * WSTRIDE;
            const float* wb4 = wb + 4 * WSTRIDE;
            uint32_t B[8][2];
            #pragma unroll
            for (int nf = 0; nf < 8; nf++) {
                const int n = nBase + nf * 8 + g;
                B[nf][0] = __float_as_uint(wb [n]);
                B[nf][1] = __float_as_uint(wb4[n]);
            }
            #pragma unroll
            for (int mf = 0; mf < 2; mf++)
                #pragma unroll
                for (int nf = 0; nf < 8; nf++)
                    mma_tf32(acc[mf][nf], A[mf], B[nf]);
        }
    }

    // ---- layer-2 epilogue: bias + silu (fp32, in regs) ----
    {
        const float* b2 = side ? be2 : bc2;
        #pragma unroll
        for (int mf = 0; mf < 2; mf++)
            #pragma unroll
            for (int nf = 0; nf < 8; nf++) {
                const int c0 = nBase + nf * 8 + 2 * tig;
                acc[mf][nf][0] = siluf(acc[mf][nf][0] + b2[c0]);
                acc[mf][nf][1] = siluf(acc[mf][nf][1] + b2[c0 + 1]);
                acc[mf][nf][2] = siluf(acc[mf][nf][2] + b2[c0]);
                acc[mf][nf][3] = siluf(acc[mf][nf][3] + b2[c0 + 1]);
            }
    }

    // ---- heads: scale = c2 @ wc3, att_pre = m2 @ wa (fp32 reductions) ----
    {
        const float* hw = side ? wa : wc3;
        float* tgt = side ? att_s : scale_s;
        #pragma unroll
        for (int mf = 0; mf < 2; mf++) {
            float p0 = 0.0f, p1 = 0.0f;
            #pragma unroll
            for (int nf = 0; nf < 8; nf++) {
                const int c0 = nBase + nf * 8 + 2 * tig;
                const float w0 = hw[c0], w1 = hw[c0 + 1];
                p0 += acc[mf][nf][0] * w0 + acc[mf][nf][1] * w1;
                p1 += acc[mf][nf][2] * w0 + acc[mf][nf][3] * w1;
            }
            p0 += __shfl_xor_sync(0xffffffffu, p0, 1);
            p0 += __shfl_xor_sync(0xffffffffu, p0, 2);
            p1 += __shfl_xor_sync(0xffffffffu, p1, 1);
            p1 += __shfl_xor_sync(0xffffffffu, p1, 2);
            if (tig == 0) {
                const int r0 = mBase + mf * 16 + g;
                atomicAdd(&tgt[r0], p0);
                atomicAdd(&tgt[r0 + 8], p1);
            }
        }
    }
    __syncthreads();

    // ---- scatter msg_h (edge side) ----
    if (side) {
        #pragma unroll
        for (int mf = 0; mf < 2; mf++) {
            const int r0 = mBase + mf * 16 + g, r1 = r0 + 8;
            const long d0 = (long)dst_s[r0] * H, d1 = (long)dst_s[r1] * H;
            const float s0 = sigf(att_s[r0]), s1 = sigf(att_s[r1]);
            #pragma unroll
            for (int nf = 0; nf < 8; nf++) {
                const int c0 = nBase + nf * 8 + 2 * tig;
                atomicAdd(&g_hagg[d0 + c0],     s0 * acc[mf][nf][0]);
                atomicAdd(&g_hagg[d0 + c0 + 1], s0 * acc[mf][nf][1]);
                atomicAdd(&g_hagg[d1 + c0],     s1 * acc[mf][nf][2]);
                atomicAdd(&g_hagg[d1 + c0 + 1], s1 * acc[mf][nf][3]);
            }
        }
    }
    // ---- scatter msg_x ----
    if (tid < TILE_M * 3) {
        const int e = tid / 3, c = tid % 3;
        const float v = scale_s[e] * diffs_s[e][c] / (rad_s[e] + 1.0f);
        atomicAdd(&g_xagg[(long)dst_s[e] * 3 + c], v);
    }
}

__global__ __launch_bounds__(128)
void node_kernel(const float* __restrict__ h, const float* __restrict__ coords,
                 const float* __restrict__ wn1, const float* __restrict__ bn1,
                 const float* __restrict__ wn2, const float* __restrict__ bn2,
                 float* __restrict__ out_h, float* __restrict__ out_x)
{
    __shared__ __align__(16) float hh_s[TILE_N][H];
    __shared__ __align__(16) float ha_s[TILE_N][H];
    __shared__ __align__(16) float n_s[TILE_N][H];

    const int tid  = threadIdx.x;
    const int warp = tid >> 5;
    const int lane = tid & 31;
    const int n0   = blockIdx.x * TILE_N;

    for (int e = warp; e < TILE_N; e += 4) {
        const int node = n0 + e;
        #pragma unroll
        for (int k = lane; k < H; k += 32) {
            hh_s[e][k] = h[(long)node * H + k];
            ha_s[e][k] = g_hagg[(long)node * H + k];
        }
    }
    __syncthreads();

    const int j = tid;
    float acc[TILE_N];
    {
        const float b1 = bn1[j];
        #pragma unroll
        for (int e = 0; e < TILE_N; e++) acc[e] = b1;
        for (int k = 0; k < H; k += 4) {
            const float wA0 = wn1[(k+0)*H + j], wA1 = wn1[(k+1)*H + j];
            const float wA2 = wn1[(k+2)*H + j], wA3 = wn1[(k+3)*H + j];
            const float wB0 = wn1[(H+k+0)*H + j], wB1 = wn1[(H+k+1)*H + j];
            const float wB2 = wn1[(H+k+2)*H + j], wB3 = wn1[(H+k+3)*H + j];
            #pragma unroll
            for (int e = 0; e < TILE_N; e++) {
                const float4 hv = *reinterpret_cast<const float4*>(&hh_s[e][k]);
                const float4 av = *reinterpret_cast<const float4*>(&ha_s[e][k]);
                float s = acc[e];
                s = fmaf(hv.x, wA0, s); s = fmaf(hv.y, wA1, s);
                s = fmaf(hv.z, wA2, s); s = fmaf(hv.w, wA3, s);
                s = fmaf(av.x, wB0, s); s = fmaf(av.y, wB1, s);
                s = fmaf(av.z, wB2, s); s = fmaf(av.w, wB3, s);
                acc[e] = s;
            }
        }
        #pragma unroll
        for (int e = 0; e < TILE_N; e++) n_s[e][j] = siluf(acc[e]);
    }
    __syncthreads();

    {
        const float b2 = bn2[j];
        #pragma unroll
        for (int e = 0; e < TILE_N; e++) acc[e] = b2;
        for (int k = 0; k < H; k += 4) {
            const float w0 = wn2[(k+0)*H + j], w1 = wn2[(k+1)*H + j];
            const float w2 = wn2[(k+2)*H + j], w3 = wn2[(k+3)*H + j];
            #pragma unroll
            for (int e = 0; e < TILE_N; e++) {
                const float4 nv = *reinterpret_cast<const float4*>(&n_s[e][k]);
                float s = acc[e];
                s = fmaf(nv.x, w0, s); s = fmaf(nv.y, w1, s);
                s = fmaf(nv.z, w2, s); s = fmaf(nv.w, w3, s);
                acc[e] = s;
            }
        }
        #pragma unroll
        for (int e = 0; e < TILE_N; e++)
            out_h[(long)(n0 + e) * H + j] = h[(long)(n0 + e) * H + j] + acc[e];
    }

    if (tid < TILE_N * 3) {
        const int e = tid / 3, c = tid % 3;
        const int node = n0 + e;
        out_x[(long)node * 3 + c] = coords[(long)node * 3 + c] + g_xagg[(long)node * 3 + c];
    }
}

extern "C" void kernel_launch(void* const* d_in, const int* in_sizes, int n_in,
                              void* d_out, int out_size) {
    const float* h      = (const float*)d_in[0];
    const float* coords = (const float*)d_in[1];
    const float* a      = (const float*)d_in[2];
    const int*   src    = (const int*)  d_in[3];
    const int*   dst    = (const int*)  d_in[4];
    const float* wc1 = (const float*)d_in[5];
    const float* bc1 = (const float*)d_in[6];
    const float* wc2 = (const float*)d_in[7];
    const float* bc2 = (const float*)d_in[8];
    const float* wc3 = (const float*)d_in[9];
    const float* we1 = (const float*)d_in[10];
    const float* be1 = (const float*)d_in[11];
    const float* we2 = (const float*)d_in[12];
    const float* be2 = (const float*)d_in[13];
    const float* wa  = (const float*)d_in[14];
    const float* ba  = (const float*)d_in[15];
    const float* wn1 = (const float*)d_in[16];
    const float* bn1 = (const float*)d_in[17];
    const float* wn2 = (const float*)d_in[18];
    const float* bn2 = (const float*)d_in[19];

    float* out_h = (float*)d_out;                 // [N, H]
    float* out_x = out_h + (long)NNODES * H;      // [N, 3]

    static bool attr_set = false;
    if (!attr_set) {
        cudaFuncSetAttribute(edge_kernel,
                             cudaFuncAttributeMaxDynamicSharedMemorySize, DYN_SMEM);
        attr_set = true;
    }

    zero_kernel<<<1024, 256>>>();
    edge_kernel<<<NEDGES / TILE_M, THREADS, DYN_SMEM>>>(h, coords, a, src, dst,
                                                        wc1, bc1, wc2, bc2, wc3,
                                                        we1, be1, we2, be2, wa, ba);
    node_kernel<<<NNODES / TILE_N, 128>>>(h, coords, wn1, bn1, wn2, bn2,
                                          out_h, out_x);
}

// round 4
// speedup vs baseline: 2.3244x; 1.0538x over previous
#include <cuda_runtime.h>
#include <cstdint>

#define NNODES 50000
#define NEDGES 800000
#define H 128
#define FE 16
#define KP1 288            // layer-1 K padded: 273 -> 288 = 9 chunks of 32
#define NCHUNK1 9
#define NCHUNK2 4
#define NCHUNKS 13
#define TILE_M 128
#define THREADS 512
#define FSTRIDE 292        // 292 % 32 == 4 -> conflict-free A frags
#define MIDSTRIDE 132      // 132 % 32 == 4
#define WSTRIDE 136        // 136 % 32 == 8 -> conflict-free B frags
#define TILE_N 8

#define W_SIDE_FLOATS (32 * WSTRIDE)       // 4352
#define W_BUF_FLOATS  (2 * W_SIDE_FLOATS)  // 8704 (both sides)
#define F_FLOATS      (TILE_M * FSTRIDE)   // 37376
#define DYN_FLOATS    (F_FLOATS + 2 * W_BUF_FLOATS)
#define DYN_SMEM      (DYN_FLOATS * 4)     // 219136 bytes

// ---------------- device globals (allocation-free scratch) ----------------
__device__ float g_w1p[2 * KP1 * H];   // tf32-rounded, zero-padded, [side][k][n]
__device__ float g_w2p[2 * H * H];     // tf32-rounded, [side][k][n]
__device__ float g_hagg[NNODES * H];
__device__ float g_xagg[NNODES * 3];

__device__ __forceinline__ float siluf(float x) { return x / (1.0f + __expf(-x)); }
__device__ __forceinline__ float sigf(float x)  { return 1.0f / (1.0f + __expf(-x)); }

__device__ __forceinline__ uint32_t cvt_tf32(float x) {
    uint32_t r; asm("cvt.rna.tf32.f32 %0, %1;" : "=r"(r) : "f"(x)); return r;
}
__device__ __forceinline__ uint32_t smem_u32(const void* p) {
    uint32_t a;
    asm("{ .reg .u64 t; cvta.to.shared.u64 t, %1; cvt.u32.u64 %0, t; }" : "=r"(a) : "l"(p));
    return a;
}
__device__ __forceinline__ void cp16(uint32_t daddr, const float* g) {
    asm volatile("cp.async.cg.shared.global [%0], [%1], 16;" :: "r"(daddr), "l"(g));
}
#define CP_COMMIT() asm volatile("cp.async.commit_group;" ::: "memory")
#define CP_WAIT1()  asm volatile("cp.async.wait_group 1;" ::: "memory")

__device__ __forceinline__ void mma_tf32(float d[4], const uint32_t a[4], const uint32_t b[2]) {
    asm volatile(
        "mma.sync.aligned.m16n8k8.row.col.f32.tf32.tf32.f32 "
        "{%0,%1,%2,%3},{%4,%5,%6,%7},{%8,%9},{%0,%1,%2,%3};"
        : "+f"(d[0]), "+f"(d[1]), "+f"(d[2]), "+f"(d[3])
        : "r"(a[0]), "r"(a[1]), "r"(a[2]), "r"(a[3]), "r"(b[0]), "r"(b[1]));
}

// ---------------- prep: round + pad weights into [side][k][n] ----------------
__global__ void prep_kernel(const float* __restrict__ wc1, const float* __restrict__ we1,
                            const float* __restrict__ wc2, const float* __restrict__ we2) {
    int i = blockIdx.x * blockDim.x + threadIdx.x;
    if (i < 2 * KP1 * H) {
        int sd = i / (KP1 * H);
        int rem = i % (KP1 * H);
        int k = rem / H, n = rem % H;
        const float* w = sd ? we1 : wc1;
        float v = (k < 273) ? w[k * H + n] : 0.0f;
        g_w1p[i] = __uint_as_float(cvt_tf32(v));
    }
    if (i < 2 * H * H) {
        int sd = i / (H * H);
        int rem = i % (H * H);
        const float* w = sd ? we2 : wc2;
        g_w2p[i] = __uint_as_float(cvt_tf32(w[rem]));
    }
}

__global__ void zero_kernel() {
    const int stride = gridDim.x * blockDim.x;
    int idx = blockIdx.x * blockDim.x + threadIdx.x;
    for (int i = idx; i < NNODES * H; i += stride) g_hagg[i] = 0.0f;
    for (int i = idx; i < NNODES * 3; i += stride) g_xagg[i] = 0.0f;
}

// stage one K=32 chunk (both sides) into w buffer `buf` via cp.async
__device__ __forceinline__ void prefetch_chunk(int c, int buf, uint32_t w_base, int tid) {
    #pragma unroll
    for (int j = 0; j < 4; j++) {
        const int idx = tid + j * THREADS;   // 0..2047
        const int sd = idx >> 10;
        const int r  = (idx >> 5) & 31;
        const int s  = idx & 31;
        const float* src = (c < NCHUNK1)
            ? g_w1p + (long)sd * KP1 * H + (long)(c * 32 + r) * H + s * 4
            : g_w2p + (long)sd * H * H + (long)((c - NCHUNK1) * 32 + r) * H + s * 4;
        const uint32_t dst = w_base +
            (uint32_t)(buf * W_BUF_FLOATS + sd * W_SIDE_FLOATS + r * WSTRIDE + s * 4) * 4u;
        cp16(dst, src);
    }
}

// --------------------------- edge kernel ---------------------------
__global__ __launch_bounds__(THREADS, 1)
void edge_kernel(const float* __restrict__ h, const float* __restrict__ coords,
                 const float* __restrict__ a, const int* __restrict__ src,
                 const int* __restrict__ dst,
                 const float* __restrict__ bc1, const float* __restrict__ bc2,
                 const float* __restrict__ wc3,
                 const float* __restrict__ be1, const float* __restrict__ be2,
                 const float* __restrict__ wa,  const float* __restrict__ ba)
{
    extern __shared__ float smem[];
    float* f_s = smem;                       // [128][FSTRIDE]
    float* w_s = smem + F_FLOATS;            // [2 bufs][2 sides][32][WSTRIDE]
    float* mid_base = smem;                  // aliases f tile after layer 1

    __shared__ float diffs_s[TILE_M][3];
    __shared__ float rad_s[TILE_M];
    __shared__ float scale_s[TILE_M];
    __shared__ float att_s[TILE_M];
    __shared__ int   src_s[TILE_M], dst_s[TILE_M];

    const int tid   = threadIdx.x;
    const int wid   = tid >> 5;
    const int lane  = tid & 31;
    const int g     = lane >> 2;
    const int tig   = lane & 3;
    const int side  = wid >> 3;           // 0=coord MLP, 1=edge MLP
    const int wloc  = wid & 7;
    const int mBase = (wloc >> 1) * 32;
    const int nBase = (wloc & 1) * 64;
    const long e0   = (long)blockIdx.x * TILE_M;

    const uint32_t w_base = smem_u32(w_s);

    // kick off first two weight-chunk prefetches before doing anything else
    prefetch_chunk(0, 0, w_base, tid); CP_COMMIT();
    prefetch_chunk(1, 1, w_base, tid); CP_COMMIT();

    // ---- per-warp prologue: indices + small-array init ----
    {
        const int eb = wid * 8;
        if (lane < 8)        src_s[eb + lane]        = src[e0 + eb + lane];
        else if (lane < 16)  dst_s[eb + lane - 8]    = dst[e0 + eb + lane - 8];
        else if (lane < 24)  scale_s[eb + lane - 16] = 0.0f;
        else                 att_s[eb + lane - 24]   = ba[0];
        __syncwarp();
        // gather 8 edges per warp
        for (int e = eb; e < eb + 8; e++) {
            const int s = src_s[e], d = dst_s[e];
            float4 hv = reinterpret_cast<const float4*>(h + (long)s * H)[lane];
            float4 dv = reinterpret_cast<const float4*>(h + (long)d * H)[lane];
            uint4 u;
            u.x = cvt_tf32(hv.x); u.y = cvt_tf32(hv.y); u.z = cvt_tf32(hv.z); u.w = cvt_tf32(hv.w);
            *reinterpret_cast<uint4*>(f_s + e * FSTRIDE + lane * 4) = u;
            u.x = cvt_tf32(dv.x); u.y = cvt_tf32(dv.y); u.z = cvt_tf32(dv.z); u.w = cvt_tf32(dv.w);
            *reinterpret_cast<uint4*>(f_s + e * FSTRIDE + H + lane * 4) = u;
            if (lane < 16)
                f_s[e * FSTRIDE + 257 + lane] =
                    __uint_as_float(cvt_tf32(a[(e0 + e) * FE + lane]));
            else if (lane >= 17)
                f_s[e * FSTRIDE + 273 + (lane - 17)] = 0.0f;   // pad to 288
            if (lane < 3)
                diffs_s[e][lane] = coords[(long)s * 3 + lane] - coords[(long)d * 3 + lane];
            __syncwarp();
            if (lane == 0) {
                float dx = diffs_s[e][0], dy = diffs_s[e][1], dz = diffs_s[e][2];
                float r = dx * dx + dy * dy + dz * dz;
                rad_s[e] = r;
                f_s[e * FSTRIDE + 256] = __uint_as_float(cvt_tf32(r));
            }
        }
    }
    __syncthreads();

    float acc[2][8][4];
    #pragma unroll
    for (int mf = 0; mf < 2; mf++)
        #pragma unroll
        for (int nf = 0; nf < 8; nf++)
            #pragma unroll
            for (int q = 0; q < 4; q++) acc[mf][nf][q] = 0.0f;

    float* mid = mid_base + (long)side * TILE_M * MIDSTRIDE;

    // ============ pipelined mainloop: 9 W1 chunks then 4 W2 chunks ============
    for (int c = 0; c < NCHUNKS; c++) {
        if (c == NCHUNK1) {
            // ---- layer-1 epilogue: acc -> silu -> mid (aliases f tile) ----
            __syncthreads();   // all frag reads of f_s complete
            const float* b1 = side ? be1 : bc1;
            #pragma unroll
            for (int mf = 0; mf < 2; mf++) {
                float* r0 = mid + (mBase + mf * 16 + g) * MIDSTRIDE;
                float* r1 = r0 + 8 * MIDSTRIDE;
                #pragma unroll
                for (int nf = 0; nf < 8; nf++) {
                    const int c0 = nBase + nf * 8 + 2 * tig;
                    const float bv0 = b1[c0], bv1 = b1[c0 + 1];
                    r0[c0]     = __uint_as_float(cvt_tf32(siluf(acc[mf][nf][0] + bv0)));
                    r0[c0 + 1] = __uint_as_float(cvt_tf32(siluf(acc[mf][nf][1] + bv1)));
                    r1[c0]     = __uint_as_float(cvt_tf32(siluf(acc[mf][nf][2] + bv0)));
                    r1[c0 + 1] = __uint_as_float(cvt_tf32(siluf(acc[mf][nf][3] + bv1)));
                    #pragma unroll
                    for (int q = 0; q < 4; q++) acc[mf][nf][q] = 0.0f;
                }
            }
            __syncthreads();
        }

        CP_WAIT1();
        __syncthreads();

        const float* wchunk = w_s + (c & 1) * W_BUF_FLOATS + side * W_SIDE_FLOATS;
        const float* Abase;
        int astr, kbase;
        if (c < NCHUNK1) { Abase = f_s; astr = FSTRIDE; kbase = c * 32; }
        else             { Abase = mid; astr = MIDSTRIDE; kbase = (c - NCHUNK1) * 32; }

        #pragma unroll
        for (int ks = 0; ks < 4; ks++) {
            const int k0 = kbase + ks * 8;
            uint32_t A[2][4];
            #pragma unroll
            for (int mf = 0; mf < 2; mf++) {
                const float* fr  = Abase + (mBase + mf * 16 + g) * astr;
                const float* fr8 = fr + 8 * astr;
                A[mf][0] = __float_as_uint(fr [k0 + tig]);
                A[mf][1] = __float_as_uint(fr8[k0 + tig]);
                A[mf][2] = __float_as_uint(fr [k0 + tig + 4]);
                A[mf][3] = __float_as_uint(fr8[k0 + tig + 4]);
            }
            const float* wb  = wchunk + (ks * 8 + tig) * WSTRIDE;
            const float* wb4 = wb + 4 * WSTRIDE;
            uint32_t B[8][2];
            #pragma unroll
            for (int nf = 0; nf < 8; nf++) {
                const int n = nBase + nf * 8 + g;
                B[nf][0] = __float_as_uint(wb [n]);
                B[nf][1] = __float_as_uint(wb4[n]);
            }
            #pragma unroll
            for (int mf = 0; mf < 2; mf++)
                #pragma unroll
                for (int nf = 0; nf < 8; nf++)
                    mma_tf32(acc[mf][nf], A[mf], B[nf]);
        }

        __syncthreads();   // frag loads of buf (c&1) done -> safe to refill
        if (c + 2 < NCHUNKS) prefetch_chunk(c + 2, c & 1, w_base, tid);
        CP_COMMIT();       // commit every iter to keep wait_group accounting simple
    }

    // ---- layer-2 epilogue: bias + silu (fp32, in regs) ----
    {
        const float* b2 = side ? be2 : bc2;
        #pragma unroll
        for (int mf = 0; mf < 2; mf++)
            #pragma unroll
            for (int nf = 0; nf < 8; nf++) {
                const int c0 = nBase + nf * 8 + 2 * tig;
                acc[mf][nf][0] = siluf(acc[mf][nf][0] + b2[c0]);
                acc[mf][nf][1] = siluf(acc[mf][nf][1] + b2[c0 + 1]);
                acc[mf][nf][2] = siluf(acc[mf][nf][2] + b2[c0]);
                acc[mf][nf][3] = siluf(acc[mf][nf][3] + b2[c0 + 1]);
            }
    }

    // ---- heads: scale = c2 @ wc3, att_pre = m2 @ wa ----
    {
        const float* hw = side ? wa : wc3;
        float* tgt = side ? att_s : scale_s;
        #pragma unroll
        for (int mf = 0; mf < 2; mf++) {
            float p0 = 0.0f, p1 = 0.0f;
            #pragma unroll
            for (int nf = 0; nf < 8; nf++) {
                const int c0 = nBase + nf * 8 + 2 * tig;
                const float w0 = hw[c0], w1 = hw[c0 + 1];
                p0 += acc[mf][nf][0] * w0 + acc[mf][nf][1] * w1;
                p1 += acc[mf][nf][2] * w0 + acc[mf][nf][3] * w1;
            }
            p0 += __shfl_xor_sync(0xffffffffu, p0, 1);
            p0 += __shfl_xor_sync(0xffffffffu, p0, 2);
            p1 += __shfl_xor_sync(0xffffffffu, p1, 1);
            p1 += __shfl_xor_sync(0xffffffffu, p1, 2);
            if (tig == 0) {
                const int r0 = mBase + mf * 16 + g;
                atomicAdd(&tgt[r0], p0);
                atomicAdd(&tgt[r0 + 8], p1);
            }
        }
    }
    __syncthreads();

    // ---- scatter msg_h (edge side) ----
    if (side) {
        #pragma unroll
        for (int mf = 0; mf < 2; mf++) {
            const int r0 = mBase + mf * 16 + g, r1 = r0 + 8;
            const long d0 = (long)dst_s[r0] * H, d1 = (long)dst_s[r1] * H;
            const float s0 = sigf(att_s[r0]), s1 = sigf(att_s[r1]);
            #pragma unroll
            for (int nf = 0; nf < 8; nf++) {
                const int c0 = nBase + nf * 8 + 2 * tig;
                atomicAdd(&g_hagg[d0 + c0],     s0 * acc[mf][nf][0]);
                atomicAdd(&g_hagg[d0 + c0 + 1], s0 * acc[mf][nf][1]);
                atomicAdd(&g_hagg[d1 + c0],     s1 * acc[mf][nf][2]);
                atomicAdd(&g_hagg[d1 + c0 + 1], s1 * acc[mf][nf][3]);
            }
        }
    }
    // ---- scatter msg_x ----
    if (tid < TILE_M * 3) {
        const int e = tid / 3, c = tid % 3;
        const float v = scale_s[e] * diffs_s[e][c] / (rad_s[e] + 1.0f);
        atomicAdd(&g_xagg[(long)dst_s[e] * 3 + c], v);
    }
}

// --------------------------- node kernel ---------------------------
__global__ __launch_bounds__(128)
void node_kernel(const float* __restrict__ h, const float* __restrict__ coords,
                 const float* __restrict__ wn1, const float* __restrict__ bn1,
                 const float* __restrict__ wn2, const float* __restrict__ bn2,
                 float* __restrict__ out_h, float* __restrict__ out_x)
{
    __shared__ __align__(16) float hh_s[TILE_N][H];
    __shared__ __align__(16) float ha_s[TILE_N][H];
    __shared__ __align__(16) float n_s[TILE_N][H];

    const int tid  = threadIdx.x;
    const int warp = tid >> 5;
    const int lane = tid & 31;
    const int n0   = blockIdx.x * TILE_N;

    for (int e = warp; e < TILE_N; e += 4) {
        const int node = n0 + e;
        #pragma unroll
        for (int k = lane; k < H; k += 32) {
            hh_s[e][k] = h[(long)node * H + k];
            ha_s[e][k] = g_hagg[(long)node * H + k];
        }
    }
    __syncthreads();

    const int j = tid;
    float acc[TILE_N];
    {
        const float b1 = bn1[j];
        #pragma unroll
        for (int e = 0; e < TILE_N; e++) acc[e] = b1;
        for (int k = 0; k < H; k += 4) {
            const float wA0 = wn1[(k+0)*H + j], wA1 = wn1[(k+1)*H + j];
            const float wA2 = wn1[(k+2)*H + j], wA3 = wn1[(k+3)*H + j];
            const float wB0 = wn1[(H+k+0)*H + j], wB1 = wn1[(H+k+1)*H + j];
            const float wB2 = wn1[(H+k+2)*H + j], wB3 = wn1[(H+k+3)*H + j];
            #pragma unroll
            for (int e = 0; e < TILE_N; e++) {
                const float4 hv = *reinterpret_cast<const float4*>(&hh_s[e][k]);
                const float4 av = *reinterpret_cast<const float4*>(&ha_s[e][k]);
                float s = acc[e];
                s = fmaf(hv.x, wA0, s); s = fmaf(hv.y, wA1, s);
                s = fmaf(hv.z, wA2, s); s = fmaf(hv.w, wA3, s);
                s = fmaf(av.x, wB0, s); s = fmaf(av.y, wB1, s);
                s = fmaf(av.z, wB2, s); s = fmaf(av.w, wB3, s);
                acc[e] = s;
            }
        }
        #pragma unroll
        for (int e = 0; e < TILE_N; e++) n_s[e][j] = siluf(acc[e]);
    }
    __syncthreads();

    {
        const float b2 = bn2[j];
        #pragma unroll
        for (int e = 0; e < TILE_N; e++) acc[e] = b2;
        for (int k = 0; k < H; k += 4) {
            const float w0 = wn2[(k+0)*H + j], w1 = wn2[(k+1)*H + j];
            const float w2 = wn2[(k+2)*H + j], w3 = wn2[(k+3)*H + j];
            #pragma unroll
            for (int e = 0; e < TILE_N; e++) {
                const float4 nv = *reinterpret_cast<const float4*>(&n_s[e][k]);
                float s = acc[e];
                s = fmaf(nv.x, w0, s); s = fmaf(nv.y, w1, s);
                s = fmaf(nv.z, w2, s); s = fmaf(nv.w, w3, s);
                acc[e] = s;
            }
        }
        #pragma unroll
        for (int e = 0; e < TILE_N; e++)
            out_h[(long)(n0 + e) * H + j] = h[(long)(n0 + e) * H + j] + acc[e];
    }

    if (tid < TILE_N * 3) {
        const int e = tid / 3, c = tid % 3;
        const int node = n0 + e;
        out_x[(long)node * 3 + c] = coords[(long)node * 3 + c] + g_xagg[(long)node * 3 + c];
    }
}

extern "C" void kernel_launch(void* const* d_in, const int* in_sizes, int n_in,
                              void* d_out, int out_size) {
    const float* h      = (const float*)d_in[0];
    const float* coords = (const float*)d_in[1];
    const float* a      = (const float*)d_in[2];
    const int*   src    = (const int*)  d_in[3];
    const int*   dst    = (const int*)  d_in[4];
    const float* wc1 = (const float*)d_in[5];
    const float* bc1 = (const float*)d_in[6];
    const float* wc2 = (const float*)d_in[7];
    const float* bc2 = (const float*)d_in[8];
    const float* wc3 = (const float*)d_in[9];
    const float* we1 = (const float*)d_in[10];
    const float* be1 = (const float*)d_in[11];
    const float* we2 = (const float*)d_in[12];
    const float* be2 = (const float*)d_in[13];
    const float* wa  = (const float*)d_in[14];
    const float* ba  = (const float*)d_in[15];
    const float* wn1 = (const float*)d_in[16];
    const float* bn1 = (const float*)d_in[17];
    const float* wn2 = (const float*)d_in[18];
    const float* bn2 = (const float*)d_in[19];

    float* out_h = (float*)d_out;
    float* out_x = out_h + (long)NNODES * H;

    static bool attr_set = false;
    if (!attr_set) {
        cudaFuncSetAttribute(edge_kernel,
                             cudaFuncAttributeMaxDynamicSharedMemorySize, DYN_SMEM);
        attr_set = true;
    }

    prep_kernel<<<(2 * KP1 * H + 255) / 256, 256>>>(wc1, we1, wc2, we2);
    zero_kernel<<<1024, 256>>>();
    edge_kernel<<<NEDGES / TILE_M, THREADS, DYN_SMEM>>>(h, coords, a, src, dst,
                                                        bc1, bc2, wc3, be1, be2, wa, ba);
    node_kernel<<<NNODES / TILE_N, 128>>>(h, coords, wn1, bn1, wn2, bn2,
                                          out_h, out_x);
}

// round 5
// speedup vs baseline: 2.9214x; 1.2569x over previous
#include <cuda_runtime.h>
#include <cuda_fp16.h>
#include <cstdint>

#define NNODES 50000
#define NEDGES 800000
#define H 128
#define FE 16
#define KP1 288            // layer-1 K padded: 273 -> 288 = 9 chunks of 32
#define NCHUNK1 9
#define NCHUNKS 13
#define TILE_M 128
#define THREADS 512
#define TILE_N 8

// fp16 strides (in half elements)
#define FS16   296         // F tile row stride: 148 words, 148%32=20 -> conflict-free
#define MIDS16 136         // mid row stride: 68 words, 68%32=4 -> conflict-free
#define WS16   40          // weight chunk row stride: 20 words -> conflict-free

#define W_SIDE_HALVES (128 * WS16)            // 5120
#define W_BUF_HALVES  (2 * W_SIDE_HALVES)     // 10240
#define F_HALVES      (TILE_M * FS16)         // 37888
#define DYN_SMEM      ((F_HALVES + 2 * W_BUF_HALVES) * 2)   // 116736 bytes

// ---------------- device globals (allocation-free scratch) ----------------
__device__ __half g_w1h[2 * 128 * KP1];   // [side][n][k] fp16 (W1^T, zero-padded)
__device__ __half g_w2h[2 * 128 * 128];   // [side][n][k] fp16 (W2^T)
__device__ float g_hagg[NNODES * H];
__device__ float g_xagg[NNODES * 3];

__device__ __forceinline__ float siluf(float x) { return x / (1.0f + __expf(-x)); }
__device__ __forceinline__ float sigf(float x)  { return 1.0f / (1.0f + __expf(-x)); }

__device__ __forceinline__ uint32_t smem_u32(const void* p) {
    uint32_t a;
    asm("{ .reg .u64 t; cvta.to.shared.u64 t, %1; cvt.u32.u64 %0, t; }" : "=r"(a) : "l"(p));
    return a;
}
__device__ __forceinline__ void cp16(uint32_t daddr, const void* g) {
    asm volatile("cp.async.cg.shared.global [%0], [%1], 16;" :: "r"(daddr), "l"(g));
}
#define CP_COMMIT() asm volatile("cp.async.commit_group;" ::: "memory")
#define CP_WAIT1()  asm volatile("cp.async.wait_group 1;" ::: "memory")

__device__ __forceinline__ void mma_f16(float d[4], const uint32_t a[4], const uint32_t b[2]) {
    asm volatile(
        "mma.sync.aligned.m16n8k16.row.col.f32.f16.f16.f32 "
        "{%0,%1,%2,%3},{%4,%5,%6,%7},{%8,%9},{%0,%1,%2,%3};"
        : "+f"(d[0]), "+f"(d[1]), "+f"(d[2]), "+f"(d[3])
        : "r"(a[0]), "r"(a[1]), "r"(a[2]), "r"(a[3]), "r"(b[0]), "r"(b[1]));
}

// ---------------- prep: transpose + fp16-round weights into [side][n][k] ----------------
__global__ void prep_kernel(const float* __restrict__ wc1, const float* __restrict__ we1,
                            const float* __restrict__ wc2, const float* __restrict__ we2) {
    int i = blockIdx.x * blockDim.x + threadIdx.x;
    if (i < 2 * 128 * KP1) {
        int sd = i / (128 * KP1);
        int rem = i % (128 * KP1);
        int n = rem / KP1, k = rem % KP1;
        const float* w = sd ? we1 : wc1;
        float v = (k < 273) ? w[k * H + n] : 0.0f;
        g_w1h[i] = __float2half_rn(v);
    }
    if (i < 2 * 128 * 128) {
        int sd = i / (128 * 128);
        int rem = i % (128 * 128);
        int n = rem / 128, k = rem % 128;
        const float* w = sd ? we2 : wc2;
        g_w2h[i] = __float2half_rn(w[k * H + n]);
    }
}

__global__ void zero_kernel() {
    const int stride = gridDim.x * blockDim.x;
    int idx = blockIdx.x * blockDim.x + threadIdx.x;
    for (int i = idx; i < NNODES * H; i += stride) g_hagg[i] = 0.0f;
    for (int i = idx; i < NNODES * 3; i += stride) g_xagg[i] = 0.0f;
}

// stage one K=32 chunk (both sides, [n=128][32 halves]) into w buffer `buf`
__device__ __forceinline__ void prefetch_chunk(int c, int buf, uint32_t w_base, int tid) {
    #pragma unroll
    for (int j = 0; j < 2; j++) {
        const int idx = tid + j * THREADS;   // 0..1023
        const int sd = idx >> 9;
        const int r  = (idx >> 2) & 127;     // n row
        const int q  = idx & 3;              // 8-half (16B) sub-block
        const __half* src = (c < NCHUNK1)
            ? g_w1h + (long)sd * 128 * KP1 + (long)r * KP1 + c * 32 + q * 8
            : g_w2h + (long)sd * 128 * 128 + (long)r * 128 + (c - NCHUNK1) * 32 + q * 8;
        const uint32_t dst = w_base +
            (uint32_t)(buf * W_BUF_HALVES + sd * W_SIDE_HALVES + r * WS16 + q * 8) * 2u;
        cp16(dst, src);
    }
}

// --------------------------- edge kernel ---------------------------
__global__ __launch_bounds__(THREADS, 1)
void edge_kernel(const float* __restrict__ h, const float* __restrict__ coords,
                 const float* __restrict__ a, const int* __restrict__ src,
                 const int* __restrict__ dst,
                 const float* __restrict__ bc1, const float* __restrict__ bc2,
                 const float* __restrict__ wc3,
                 const float* __restrict__ be1, const float* __restrict__ be2,
                 const float* __restrict__ wa,  const float* __restrict__ ba)
{
    extern __shared__ __half smem_h[];
    __half* f_h = smem_h;                       // [128][FS16]
    __half* w_h = smem_h + F_HALVES;            // [2 bufs][2 sides][128][WS16]
    __half* mid_base = smem_h;                  // aliases f tile after layer 1

    __shared__ float diffs_s[TILE_M][3];
    __shared__ float rad_s[TILE_M];
    __shared__ float scale_s[TILE_M];
    __shared__ float att_s[TILE_M];
    __shared__ int   src_s[TILE_M], dst_s[TILE_M];

    const int tid   = threadIdx.x;
    const int wid   = tid >> 5;
    const int lane  = tid & 31;
    const int g     = lane >> 2;
    const int tig   = lane & 3;
    const int side  = wid >> 3;           // 0=coord MLP, 1=edge MLP
    const int wloc  = wid & 7;
    const int mBase = (wloc >> 1) * 32;
    const int nBase = (wloc & 1) * 64;
    const long e0   = (long)blockIdx.x * TILE_M;

    const uint32_t w_base = smem_u32(w_h);

    // kick off first two weight-chunk prefetches
    prefetch_chunk(0, 0, w_base, tid); CP_COMMIT();
    prefetch_chunk(1, 1, w_base, tid); CP_COMMIT();

    // ---- per-warp prologue: indices + gather (fp16 conversion) ----
    {
        const int eb = wid * 8;
        if (lane < 8)        src_s[eb + lane]        = src[e0 + eb + lane];
        else if (lane < 16)  dst_s[eb + lane - 8]    = dst[e0 + eb + lane - 8];
        else if (lane < 24)  scale_s[eb + lane - 16] = 0.0f;
        else                 att_s[eb + lane - 24]   = ba[0];
        __syncwarp();
        for (int e = eb; e < eb + 8; e++) {
            const int s = src_s[e], d = dst_s[e];
            float4 hv = reinterpret_cast<const float4*>(h + (long)s * H)[lane];
            float4 dv = reinterpret_cast<const float4*>(h + (long)d * H)[lane];
            __half2 p0 = __floats2half2_rn(hv.x, hv.y);
            __half2 p1 = __floats2half2_rn(hv.z, hv.w);
            *reinterpret_cast<__half2*>(f_h + e * FS16 + lane * 4)     = p0;
            *reinterpret_cast<__half2*>(f_h + e * FS16 + lane * 4 + 2) = p1;
            p0 = __floats2half2_rn(dv.x, dv.y);
            p1 = __floats2half2_rn(dv.z, dv.w);
            *reinterpret_cast<__half2*>(f_h + e * FS16 + H + lane * 4)     = p0;
            *reinterpret_cast<__half2*>(f_h + e * FS16 + H + lane * 4 + 2) = p1;
            if (lane < 16)
                f_h[e * FS16 + 257 + lane] = __float2half_rn(a[(e0 + e) * FE + lane]);
            else if (lane >= 17)
                f_h[e * FS16 + 273 + (lane - 17)] = __float2half_rn(0.0f); // pad to 288
            if (lane < 3)
                diffs_s[e][lane] = coords[(long)s * 3 + lane] - coords[(long)d * 3 + lane];
            __syncwarp();
            if (lane == 0) {
                float dx = diffs_s[e][0], dy = diffs_s[e][1], dz = diffs_s[e][2];
                float r = dx * dx + dy * dy + dz * dz;
                rad_s[e] = r;
                f_h[e * FS16 + 256] = __float2half_rn(r);
            }
        }
    }
    __syncthreads();

    float acc[2][8][4];
    #pragma unroll
    for (int mf = 0; mf < 2; mf++)
        #pragma unroll
        for (int nf = 0; nf < 8; nf++)
            #pragma unroll
            for (int q = 0; q < 4; q++) acc[mf][nf][q] = 0.0f;

    __half* mid = mid_base + (long)side * TILE_M * MIDS16;

    // ============ pipelined mainloop: 9 W1 chunks then 4 W2 chunks ============
    for (int c = 0; c < NCHUNKS; c++) {
        if (c == NCHUNK1) {
            // ---- layer-1 epilogue: acc -> silu -> mid fp16 (aliases f tile) ----
            __syncthreads();
            const float* b1 = side ? be1 : bc1;
            #pragma unroll
            for (int mf = 0; mf < 2; mf++) {
                __half* r0 = mid + (mBase + mf * 16 + g) * MIDS16;
                __half* r1 = r0 + 8 * MIDS16;
                #pragma unroll
                for (int nf = 0; nf < 8; nf++) {
                    const int c0 = nBase + nf * 8 + 2 * tig;
                    const float bv0 = b1[c0], bv1 = b1[c0 + 1];
                    *reinterpret_cast<__half2*>(r0 + c0) =
                        __floats2half2_rn(siluf(acc[mf][nf][0] + bv0), siluf(acc[mf][nf][1] + bv1));
                    *reinterpret_cast<__half2*>(r1 + c0) =
                        __floats2half2_rn(siluf(acc[mf][nf][2] + bv0), siluf(acc[mf][nf][3] + bv1));
                    #pragma unroll
                    for (int q = 0; q < 4; q++) acc[mf][nf][q] = 0.0f;
                }
            }
            __syncthreads();
        }

        CP_WAIT1();
        __syncthreads();

        const uint32_t* ww = reinterpret_cast<const uint32_t*>(w_h) +
                             ((c & 1) * W_BUF_HALVES + side * W_SIDE_HALVES) / 2;
        const uint32_t* Aw;
        int awstr, kwbase;
        if (c < NCHUNK1) { Aw = reinterpret_cast<const uint32_t*>(f_h); awstr = FS16 / 2;   kwbase = c * 16; }
        else             { Aw = reinterpret_cast<const uint32_t*>(mid); awstr = MIDS16 / 2; kwbase = (c - NCHUNK1) * 16; }

        #pragma unroll
        for (int ks = 0; ks < 2; ks++) {
            const int kw = kwbase + ks * 8;      // word offset (2 halves/word), k16 step
            uint32_t A[2][4];
            #pragma unroll
            for (int mf = 0; mf < 2; mf++) {
                const uint32_t* fr  = Aw + (mBase + mf * 16 + g) * awstr;
                const uint32_t* fr8 = fr + 8 * awstr;
                A[mf][0] = fr [kw + tig];
                A[mf][1] = fr8[kw + tig];
                A[mf][2] = fr [kw + tig + 4];
                A[mf][3] = fr8[kw + tig + 4];
            }
            const int bw = ks * 8 + tig;         // word offset within 32-half chunk row
            uint32_t B[8][2];
            #pragma unroll
            for (int nf = 0; nf < 8; nf++) {
                const uint32_t* br = ww + (nBase + nf * 8 + g) * (WS16 / 2);
                B[nf][0] = br[bw];
                B[nf][1] = br[bw + 4];
            }
            #pragma unroll
            for (int mf = 0; mf < 2; mf++)
                #pragma unroll
                for (int nf = 0; nf < 8; nf++)
                    mma_f16(acc[mf][nf], A[mf], B[nf]);
        }

        __syncthreads();   // frag loads of buf (c&1) done -> safe to refill
        if (c + 2 < NCHUNKS) prefetch_chunk(c + 2, c & 1, w_base, tid);
        CP_COMMIT();
    }

    // ---- layer-2 epilogue: bias + silu (fp32, in regs) ----
    {
        const float* b2 = side ? be2 : bc2;
        #pragma unroll
        for (int mf = 0; mf < 2; mf++)
            #pragma unroll
            for (int nf = 0; nf < 8; nf++) {
                const int c0 = nBase + nf * 8 + 2 * tig;
                acc[mf][nf][0] = siluf(acc[mf][nf][0] + b2[c0]);
                acc[mf][nf][1] = siluf(acc[mf][nf][1] + b2[c0 + 1]);
                acc[mf][nf][2] = siluf(acc[mf][nf][2] + b2[c0]);
                acc[mf][nf][3] = siluf(acc[mf][nf][3] + b2[c0 + 1]);
            }
    }

    // ---- heads: scale = c2 @ wc3, att_pre = m2 @ wa ----
    {
        const float* hw = side ? wa : wc3;
        float* tgt = side ? att_s : scale_s;
        #pragma unroll
        for (int mf = 0; mf < 2; mf++) {
            float p0 = 0.0f, p1 = 0.0f;
            #pragma unroll
            for (int nf = 0; nf < 8; nf++) {
                const int c0 = nBase + nf * 8 + 2 * tig;
                const float w0 = hw[c0], w1 = hw[c0 + 1];
                p0 += acc[mf][nf][0] * w0 + acc[mf][nf][1] * w1;
                p1 += acc[mf][nf][2] * w0 + acc[mf][nf][3] * w1;
            }
            p0 += __shfl_xor_sync(0xffffffffu, p0, 1);
            p0 += __shfl_xor_sync(0xffffffffu, p0, 2);
            p1 += __shfl_xor_sync(0xffffffffu, p1, 1);
            p1 += __shfl_xor_sync(0xffffffffu, p1, 2);
            if (tig == 0) {
                const int r0 = mBase + mf * 16 + g;
                atomicAdd(&tgt[r0], p0);
                atomicAdd(&tgt[r0 + 8], p1);
            }
        }
    }
    __syncthreads();

    // ---- scatter msg_h (edge side) ----
    if (side) {
        #pragma unroll
        for (int mf = 0; mf < 2; mf++) {
            const int r0 = mBase + mf * 16 + g, r1 = r0 + 8;
            const long d0 = (long)dst_s[r0] * H, d1 = (long)dst_s[r1] * H;
            const float s0 = sigf(att_s[r0]), s1 = sigf(att_s[r1]);
            #pragma unroll
            for (int nf = 0; nf < 8; nf++) {
                const int c0 = nBase + nf * 8 + 2 * tig;
                atomicAdd(&g_hagg[d0 + c0],     s0 * acc[mf][nf][0]);
                atomicAdd(&g_hagg[d0 + c0 + 1], s0 * acc[mf][nf][1]);
                atomicAdd(&g_hagg[d1 + c0],     s1 * acc[mf][nf][2]);
                atomicAdd(&g_hagg[d1 + c0 + 1], s1 * acc[mf][nf][3]);
            }
        }
    }
    // ---- scatter msg_x ----
    if (tid < TILE_M * 3) {
        const int e = tid / 3, c = tid % 3;
        const float v = scale_s[e] * diffs_s[e][c] / (rad_s[e] + 1.0f);
        atomicAdd(&g_xagg[(long)dst_s[e] * 3 + c], v);
    }
}

// --------------------------- node kernel ---------------------------
__global__ __launch_bounds__(128)
void node_kernel(const float* __restrict__ h, const float* __restrict__ coords,
                 const float* __restrict__ wn1, const float* __restrict__ bn1,
                 const float* __restrict__ wn2, const float* __restrict__ bn2,
                 float* __restrict__ out_h, float* __restrict__ out_x)
{
    __shared__ __align__(16) float hh_s[TILE_N][H];
    __shared__ __align__(16) float ha_s[TILE_N][H];
    __shared__ __align__(16) float n_s[TILE_N][H];

    const int tid  = threadIdx.x;
    const int warp = tid >> 5;
    const int lane = tid & 31;
    const int n0   = blockIdx.x * TILE_N;

    for (int e = warp; e < TILE_N; e += 4) {
        const int node = n0 + e;
        #pragma unroll
        for (int k = lane; k < H; k += 32) {
            hh_s[e][k] = h[(long)node * H + k];
            ha_s[e][k] = g_hagg[(long)node * H + k];
        }
    }
    __syncthreads();

    const int j = tid;
    float acc[TILE_N];
    {
        const float b1 = bn1[j];
        #pragma unroll
        for (int e = 0; e < TILE_N; e++) acc[e] = b1;
        for (int k = 0; k < H; k += 4) {
            const float wA0 = wn1[(k+0)*H + j], wA1 = wn1[(k+1)*H + j];
            const float wA2 = wn1[(k+2)*H + j], wA3 = wn1[(k+3)*H + j];
            const float wB0 = wn1[(H+k+0)*H + j], wB1 = wn1[(H+k+1)*H + j];
            const float wB2 = wn1[(H+k+2)*H + j], wB3 = wn1[(H+k+3)*H + j];
            #pragma unroll
            for (int e = 0; e < TILE_N; e++) {
                const float4 hv = *reinterpret_cast<const float4*>(&hh_s[e][k]);
                const float4 av = *reinterpret_cast<const float4*>(&ha_s[e][k]);
                float s = acc[e];
                s = fmaf(hv.x, wA0, s); s = fmaf(hv.y, wA1, s);
                s = fmaf(hv.z, wA2, s); s = fmaf(hv.w, wA3, s);
                s = fmaf(av.x, wB0, s); s = fmaf(av.y, wB1, s);
                s = fmaf(av.z, wB2, s); s = fmaf(av.w, wB3, s);
                acc[e] = s;
            }
        }
        #pragma unroll
        for (int e = 0; e < TILE_N; e++) n_s[e][j] = siluf(acc[e]);
    }
    __syncthreads();

    {
        const float b2 = bn2[j];
        #pragma unroll
        for (int e = 0; e < TILE_N; e++) acc[e] = b2;
        for (int k = 0; k < H; k += 4) {
            const float w0 = wn2[(k+0)*H + j], w1 = wn2[(k+1)*H + j];
            const float w2 = wn2[(k+2)*H + j], w3 = wn2[(k+3)*H + j];
            #pragma unroll
            for (int e = 0; e < TILE_N; e++) {
                const float4 nv = *reinterpret_cast<const float4*>(&n_s[e][k]);
                float s = acc[e];
                s = fmaf(nv.x, w0, s); s = fmaf(nv.y, w1, s);
                s = fmaf(nv.z, w2, s); s = fmaf(nv.w, w3, s);
                acc[e] = s;
            }
        }
        #pragma unroll
        for (int e = 0; e < TILE_N; e++)
            out_h[(long)(n0 + e) * H + j] = h[(long)(n0 + e) * H + j] + acc[e];
    }

    if (tid < TILE_N * 3) {
        const int e = tid / 3, c = tid % 3;
        const int node = n0 + e;
        out_x[(long)node * 3 + c] = coords[(long)node * 3 + c] + g_xagg[(long)node * 3 + c];
    }
}

extern "C" void kernel_launch(void* const* d_in, const int* in_sizes, int n_in,
                              void* d_out, int out_size) {
    const float* h      = (const float*)d_in[0];
    const float* coords = (const float*)d_in[1];
    const float* a      = (const float*)d_in[2];
    const int*   src    = (const int*)  d_in[3];
    const int*   dst    = (const int*)  d_in[4];
    const float* wc1 = (const float*)d_in[5];
    const float* bc1 = (const float*)d_in[6];
    const float* wc2 = (const float*)d_in[7];
    const float* bc2 = (const float*)d_in[8];
    const float* wc3 = (const float*)d_in[9];
    const float* we1 = (const float*)d_in[10];
    const float* be1 = (const float*)d_in[11];
    const float* we2 = (const float*)d_in[12];
    const float* be2 = (const float*)d_in[13];
    const float* wa  = (const float*)d_in[14];
    const float* ba  = (const float*)d_in[15];
    const float* wn1 = (const float*)d_in[16];
    const float* bn1 = (const float*)d_in[17];
    const float* wn2 = (const float*)d_in[18];
    const float* bn2 = (const float*)d_in[19];

    float* out_h = (float*)d_out;
    float* out_x = out_h + (long)NNODES * H;

    static bool attr_set = false;
    if (!attr_set) {
        cudaFuncSetAttribute(edge_kernel,
                             cudaFuncAttributeMaxDynamicSharedMemorySize, DYN_SMEM);
        attr_set = true;
    }

    prep_kernel<<<(2 * 128 * KP1 + 255) / 256, 256>>>(wc1, we1, wc2, we2);
    zero_kernel<<<1024, 256>>>();
    edge_kernel<<<NEDGES / TILE_M, THREADS, DYN_SMEM>>>(h, coords, a, src, dst,
                                                        bc1, bc2, wc3, be1, be2, wa, ba);
    node_kernel<<<NNODES / TILE_N, 128>>>(h, coords, wn1, bn1, wn2, bn2,
                                          out_h, out_x);
}